// round 1
// baseline (speedup 1.0000x reference)
#include <cuda_runtime.h>
#include <math.h>

// ---------------------------------------------------------------------------
// EaULoss: fused masked tanh-product reduction.
//   a = (e<=eth) ? (1-tanh e) : tanh e
//   b = (u<=uth) ? (1-tanh u) : tanh u
//   den = sum(a*b);  num = sum(a*b where predicates agree)
//   loss = -log( num/(den+1e-10) + 1e-10 )
// Deterministic two-pass reduction (no float atomics).
// ---------------------------------------------------------------------------

#define NBLK   1024
#define NTHR   256
#define EPS_F  1e-10f

__device__ float g_num[NBLK];
__device__ float g_den[NBLK];

__device__ __forceinline__ void accum(float e, float u, float eth, float uth,
                                      float& num, float& den) {
    float te = tanhf(e);
    float tu = tanhf(u);
    bool  le = (e <= eth);
    bool  ce = (u <= uth);
    float a  = le ? (1.0f - te) : te;
    float b  = ce ? (1.0f - tu) : tu;
    float v  = a * b;
    den += v;
    if (le == ce) num += v;   // low&certain or high&uncertain
}

__global__ __launch_bounds__(NTHR)
void eau_pass1(const float4* __restrict__ err4,
               const float4* __restrict__ unc4,
               const float*  __restrict__ eth_p,
               const float*  __restrict__ uth_p,
               int nvec, int n_total) {
    const float eth = *eth_p;
    const float uth = *uth_p;

    float num = 0.0f, den = 0.0f;

    const int stride = gridDim.x * blockDim.x;
    for (int i = blockIdx.x * blockDim.x + threadIdx.x; i < nvec; i += stride) {
        float4 e = err4[i];
        float4 u = unc4[i];
        accum(e.x, u.x, eth, uth, num, den);
        accum(e.y, u.y, eth, uth, num, den);
        accum(e.z, u.z, eth, uth, num, den);
        accum(e.w, u.w, eth, uth, num, den);
    }

    // scalar tail (n_total not divisible by 4)
    int rem_start = nvec * 4;
    int rem = n_total - rem_start;
    if (blockIdx.x == 0 && (int)threadIdx.x < rem) {
        const float* ef = (const float*)err4;
        const float* uf = (const float*)unc4;
        int j = rem_start + threadIdx.x;
        accum(ef[j], uf[j], eth, uth, num, den);
    }

    // warp reduce
    #pragma unroll
    for (int off = 16; off > 0; off >>= 1) {
        num += __shfl_xor_sync(0xFFFFFFFFu, num, off);
        den += __shfl_xor_sync(0xFFFFFFFFu, den, off);
    }

    // block reduce via shared
    __shared__ float s_num[NTHR / 32];
    __shared__ float s_den[NTHR / 32];
    int lane = threadIdx.x & 31;
    int wid  = threadIdx.x >> 5;
    if (lane == 0) { s_num[wid] = num; s_den[wid] = den; }
    __syncthreads();
    if (wid == 0) {
        num = (lane < NTHR / 32) ? s_num[lane] : 0.0f;
        den = (lane < NTHR / 32) ? s_den[lane] : 0.0f;
        #pragma unroll
        for (int off = 4; off > 0; off >>= 1) {
            num += __shfl_xor_sync(0xFFFFFFFFu, num, off);
            den += __shfl_xor_sync(0xFFFFFFFFu, den, off);
        }
        if (lane == 0) { g_num[blockIdx.x] = num; g_den[blockIdx.x] = den; }
    }
}

__global__ __launch_bounds__(NBLK)
void eau_pass2(float* __restrict__ out) {
    int tid = threadIdx.x;
    float num = g_num[tid];
    float den = g_den[tid];

    #pragma unroll
    for (int off = 16; off > 0; off >>= 1) {
        num += __shfl_xor_sync(0xFFFFFFFFu, num, off);
        den += __shfl_xor_sync(0xFFFFFFFFu, den, off);
    }

    __shared__ float s_num[NBLK / 32];
    __shared__ float s_den[NBLK / 32];
    int lane = tid & 31;
    int wid  = tid >> 5;
    if (lane == 0) { s_num[wid] = num; s_den[wid] = den; }
    __syncthreads();
    if (wid == 0) {
        num = (lane < NBLK / 32) ? s_num[lane] : 0.0f;
        den = (lane < NBLK / 32) ? s_den[lane] : 0.0f;
        #pragma unroll
        for (int off = 16; off > 0; off >>= 1) {
            num += __shfl_xor_sync(0xFFFFFFFFu, num, off);
            den += __shfl_xor_sync(0xFFFFFFFFu, den, off);
        }
        if (lane == 0) {
            float eau = num / (den + EPS_F);
            out[0] = -logf(eau + EPS_F);   // BETA = 1.0
        }
    }
}

extern "C" void kernel_launch(void* const* d_in, const int* in_sizes, int n_in,
                              void* d_out, int out_size) {
    const float* err = (const float*)d_in[0];
    const float* unc = (const float*)d_in[1];
    const float* eth = (const float*)d_in[2];
    const float* uth = (const float*)d_in[3];
    float* out = (float*)d_out;

    int n    = in_sizes[0];
    int nvec = n >> 2;

    eau_pass1<<<NBLK, NTHR>>>((const float4*)err, (const float4*)unc,
                              eth, uth, nvec, n);
    eau_pass2<<<1, NBLK>>>(out);
}

// round 2
// speedup vs baseline: 1.1887x; 1.1887x over previous
#include <cuda_runtime.h>
#include <math.h>

// ---------------------------------------------------------------------------
// EaULoss fused single-kernel reduction.
//   a = (e<=eth) ? (1-tanh e) : tanh e
//   b = (u<=uth) ? (1-tanh u) : tanh u
//   den = sum(a*b);  num = sum(a*b where predicates agree)
//   loss = -log( num/(den+1e-10) + 1e-10 )
// Last-block-finish pattern: deterministic, graph-replay-safe (counter wraps).
// ---------------------------------------------------------------------------

#define NBLK   1024
#define NTHR   256
#define EPS_F  1e-10f

__device__ float g_num[NBLK];
__device__ float g_den[NBLK];
__device__ unsigned int g_count = 0;   // wraps back to 0 every call

__device__ __forceinline__ float fast_tanh(float x) {
    float y;
    asm("tanh.approx.f32 %0, %1;" : "=f"(y) : "f"(x));
    return y;
}

__device__ __forceinline__ void accum(float e, float u, float eth, float uth,
                                      float& num, float& den) {
    float te = fast_tanh(e);
    float tu = fast_tanh(u);
    bool  le = (e <= eth);
    bool  ce = (u <= uth);
    float a  = le ? (1.0f - te) : te;
    float b  = ce ? (1.0f - tu) : tu;
    float v  = a * b;
    den += v;
    if (le == ce) num += v;   // low&certain or high&uncertain
}

__global__ __launch_bounds__(NTHR)
void eau_fused(const float4* __restrict__ err4,
               const float4* __restrict__ unc4,
               const float*  __restrict__ eth_p,
               const float*  __restrict__ uth_p,
               int nvec, int n_total,
               float* __restrict__ out) {
    const float eth = *eth_p;
    const float uth = *uth_p;

    float num = 0.0f, den = 0.0f;

    const int tid    = blockIdx.x * NTHR + threadIdx.x;
    const int stride = NBLK * NTHR;

    if (nvec == stride * 16) {
        // Exact-shape fast path: fixed trip count, batched streaming loads.
        #pragma unroll 4
        for (int k = 0; k < 16; k++) {
            int i = tid + k * stride;
            float4 e = __ldcs(&err4[i]);
            float4 u = __ldcs(&unc4[i]);
            accum(e.x, u.x, eth, uth, num, den);
            accum(e.y, u.y, eth, uth, num, den);
            accum(e.z, u.z, eth, uth, num, den);
            accum(e.w, u.w, eth, uth, num, den);
        }
    } else {
        for (int i = tid; i < nvec; i += stride) {
            float4 e = __ldcs(&err4[i]);
            float4 u = __ldcs(&unc4[i]);
            accum(e.x, u.x, eth, uth, num, den);
            accum(e.y, u.y, eth, uth, num, den);
            accum(e.z, u.z, eth, uth, num, den);
            accum(e.w, u.w, eth, uth, num, den);
        }
        // scalar tail
        int rem_start = nvec * 4;
        int rem = n_total - rem_start;
        if (blockIdx.x == 0 && (int)threadIdx.x < rem) {
            const float* ef = (const float*)err4;
            const float* uf = (const float*)unc4;
            int j = rem_start + threadIdx.x;
            accum(ef[j], uf[j], eth, uth, num, den);
        }
    }

    // ---- block reduction ----
    #pragma unroll
    for (int off = 16; off > 0; off >>= 1) {
        num += __shfl_xor_sync(0xFFFFFFFFu, num, off);
        den += __shfl_xor_sync(0xFFFFFFFFu, den, off);
    }

    __shared__ float s_num[NTHR / 32];
    __shared__ float s_den[NTHR / 32];
    int lane = threadIdx.x & 31;
    int wid  = threadIdx.x >> 5;
    if (lane == 0) { s_num[wid] = num; s_den[wid] = den; }
    __syncthreads();
    if (wid == 0) {
        num = (lane < NTHR / 32) ? s_num[lane] : 0.0f;
        den = (lane < NTHR / 32) ? s_den[lane] : 0.0f;
        #pragma unroll
        for (int off = 4; off > 0; off >>= 1) {
            num += __shfl_xor_sync(0xFFFFFFFFu, num, off);
            den += __shfl_xor_sync(0xFFFFFFFFu, den, off);
        }
        if (lane == 0) { g_num[blockIdx.x] = num; g_den[blockIdx.x] = den; }
    }

    // ---- last block finishes ----
    __shared__ bool is_last;
    __threadfence();
    if (threadIdx.x == 0) {
        unsigned prev = atomicInc(&g_count, NBLK - 1);  // wraps to 0 on last
        is_last = (prev == NBLK - 1);
    }
    __syncthreads();

    if (is_last) {
        float fn = 0.0f, fd = 0.0f;
        #pragma unroll
        for (int k = 0; k < NBLK / NTHR; k++) {
            int j = threadIdx.x + k * NTHR;
            fn += g_num[j];
            fd += g_den[j];
        }
        #pragma unroll
        for (int off = 16; off > 0; off >>= 1) {
            fn += __shfl_xor_sync(0xFFFFFFFFu, fn, off);
            fd += __shfl_xor_sync(0xFFFFFFFFu, fd, off);
        }
        if (lane == 0) { s_num[wid] = fn; s_den[wid] = fd; }
        __syncthreads();
        if (wid == 0) {
            fn = (lane < NTHR / 32) ? s_num[lane] : 0.0f;
            fd = (lane < NTHR / 32) ? s_den[lane] : 0.0f;
            #pragma unroll
            for (int off = 4; off > 0; off >>= 1) {
                fn += __shfl_xor_sync(0xFFFFFFFFu, fn, off);
                fd += __shfl_xor_sync(0xFFFFFFFFu, fd, off);
            }
            if (lane == 0) {
                float eau = fn / (fd + EPS_F);
                out[0] = -logf(eau + EPS_F);   // BETA = 1.0
            }
        }
    }
}

extern "C" void kernel_launch(void* const* d_in, const int* in_sizes, int n_in,
                              void* d_out, int out_size) {
    const float* err = (const float*)d_in[0];
    const float* unc = (const float*)d_in[1];
    const float* eth = (const float*)d_in[2];
    const float* uth = (const float*)d_in[3];
    float* out = (float*)d_out;

    int n    = in_sizes[0];
    int nvec = n >> 2;

    eau_fused<<<NBLK, NTHR>>>((const float4*)err, (const float4*)unc,
                              eth, uth, nvec, n, out);
}

// round 3
// speedup vs baseline: 1.2010x; 1.0104x over previous
#include <cuda_runtime.h>
#include <math.h>

// ---------------------------------------------------------------------------
// EaULoss fused single-kernel reduction, software-pipelined loads.
//   a = (e<=eth) ? (1-tanh e) : tanh e
//   b = (u<=uth) ? (1-tanh u) : tanh u
//   den = sum(a*b);  num = sum(a*b where predicates agree)
//   loss = -log( num/(den+1e-10) + 1e-10 )
// ---------------------------------------------------------------------------

#define NBLK   1024
#define NTHR   256
#define EPS_F  1e-10f

__device__ float g_num[NBLK];
__device__ float g_den[NBLK];
__device__ unsigned int g_count = 0;   // wraps back to 0 every call

__device__ __forceinline__ float fast_tanh(float x) {
    float y;
    asm("tanh.approx.f32 %0, %1;" : "=f"(y) : "f"(x));
    return y;
}

__device__ __forceinline__ void accum(float e, float u, float eth, float uth,
                                      float& num, float& den) {
    float te = fast_tanh(e);
    float tu = fast_tanh(u);
    bool  le = (e <= eth);
    bool  ce = (u <= uth);
    float a  = le ? (1.0f - te) : te;
    float b  = ce ? (1.0f - tu) : tu;
    float v  = a * b;
    den += v;
    if (le == ce) num += v;   // low&certain or high&uncertain
}

__device__ __forceinline__ void accum4(float4 e, float4 u, float eth, float uth,
                                       float& num, float& den) {
    accum(e.x, u.x, eth, uth, num, den);
    accum(e.y, u.y, eth, uth, num, den);
    accum(e.z, u.z, eth, uth, num, den);
    accum(e.w, u.w, eth, uth, num, den);
}

__global__ __launch_bounds__(NTHR)
void eau_fused(const float4* __restrict__ err4,
               const float4* __restrict__ unc4,
               const float*  __restrict__ eth_p,
               const float*  __restrict__ uth_p,
               int nvec, int n_total,
               float* __restrict__ out) {
    const float eth = *eth_p;
    const float uth = *uth_p;

    float num = 0.0f, den = 0.0f;

    const int base   = blockIdx.x * NTHR + threadIdx.x;
    const int stride = NBLK * NTHR;

    if (nvec == stride * 16) {
        // Exact-shape fast path: 16 float4-pairs/thread as 4 groups of 4,
        // double-buffered so 8 LDG.128 are in flight during every compute phase.
        float4 ce[4], cu[4], ne[4], nu[4];

        #pragma unroll
        for (int j = 0; j < 4; j++) {
            ce[j] = __ldcs(&err4[base + j * stride]);
            cu[j] = __ldcs(&unc4[base + j * stride]);
        }

        #pragma unroll
        for (int g = 0; g < 4; g++) {
            if (g < 3) {
                int off = base + (g + 1) * 4 * stride;
                #pragma unroll
                for (int j = 0; j < 4; j++) {
                    ne[j] = __ldcs(&err4[off + j * stride]);
                    nu[j] = __ldcs(&unc4[off + j * stride]);
                }
            }
            #pragma unroll
            for (int j = 0; j < 4; j++)
                accum4(ce[j], cu[j], eth, uth, num, den);
            if (g < 3) {
                #pragma unroll
                for (int j = 0; j < 4; j++) { ce[j] = ne[j]; cu[j] = nu[j]; }
            }
        }
    } else {
        for (int i = base; i < nvec; i += stride) {
            float4 e = __ldcs(&err4[i]);
            float4 u = __ldcs(&unc4[i]);
            accum4(e, u, eth, uth, num, den);
        }
        // scalar tail
        int rem_start = nvec * 4;
        int rem = n_total - rem_start;
        if (blockIdx.x == 0 && (int)threadIdx.x < rem) {
            const float* ef = (const float*)err4;
            const float* uf = (const float*)unc4;
            int j = rem_start + threadIdx.x;
            accum(ef[j], uf[j], eth, uth, num, den);
        }
    }

    // ---- block reduction ----
    #pragma unroll
    for (int off = 16; off > 0; off >>= 1) {
        num += __shfl_xor_sync(0xFFFFFFFFu, num, off);
        den += __shfl_xor_sync(0xFFFFFFFFu, den, off);
    }

    __shared__ float s_num[NTHR / 32];
    __shared__ float s_den[NTHR / 32];
    int lane = threadIdx.x & 31;
    int wid  = threadIdx.x >> 5;
    if (lane == 0) { s_num[wid] = num; s_den[wid] = den; }
    __syncthreads();
    if (wid == 0) {
        num = (lane < NTHR / 32) ? s_num[lane] : 0.0f;
        den = (lane < NTHR / 32) ? s_den[lane] : 0.0f;
        #pragma unroll
        for (int off = 4; off > 0; off >>= 1) {
            num += __shfl_xor_sync(0xFFFFFFFFu, num, off);
            den += __shfl_xor_sync(0xFFFFFFFFu, den, off);
        }
        if (lane == 0) { g_num[blockIdx.x] = num; g_den[blockIdx.x] = den; }
    }

    // ---- last block finishes ----
    __shared__ bool is_last;
    __threadfence();
    if (threadIdx.x == 0) {
        unsigned prev = atomicInc(&g_count, NBLK - 1);  // wraps to 0 on last
        is_last = (prev == NBLK - 1);
    }
    __syncthreads();

    if (is_last) {
        float fn = 0.0f, fd = 0.0f;
        #pragma unroll
        for (int k = 0; k < NBLK / NTHR; k++) {
            int j = threadIdx.x + k * NTHR;
            fn += g_num[j];
            fd += g_den[j];
        }
        #pragma unroll
        for (int off = 16; off > 0; off >>= 1) {
            fn += __shfl_xor_sync(0xFFFFFFFFu, fn, off);
            fd += __shfl_xor_sync(0xFFFFFFFFu, fd, off);
        }
        if (lane == 0) { s_num[wid] = fn; s_den[wid] = fd; }
        __syncthreads();
        if (wid == 0) {
            fn = (lane < NTHR / 32) ? s_num[lane] : 0.0f;
            fd = (lane < NTHR / 32) ? s_den[lane] : 0.0f;
            #pragma unroll
            for (int off = 4; off > 0; off >>= 1) {
                fn += __shfl_xor_sync(0xFFFFFFFFu, fn, off);
                fd += __shfl_xor_sync(0xFFFFFFFFu, fd, off);
            }
            if (lane == 0) {
                float eau = fn / (fd + EPS_F);
                out[0] = -logf(eau + EPS_F);   // BETA = 1.0
            }
        }
    }
}

extern "C" void kernel_launch(void* const* d_in, const int* in_sizes, int n_in,
                              void* d_out, int out_size) {
    const float* err = (const float*)d_in[0];
    const float* unc = (const float*)d_in[1];
    const float* eth = (const float*)d_in[2];
    const float* uth = (const float*)d_in[3];
    float* out = (float*)d_out;

    int n    = in_sizes[0];
    int nvec = n >> 2;

    eau_fused<<<NBLK, NTHR>>>((const float4*)err, (const float4*)unc,
                              eth, uth, nvec, n, out);
}

// round 5
// speedup vs baseline: 1.2868x; 1.0714x over previous
#include <cuda_runtime.h>
#include <math.h>

// ---------------------------------------------------------------------------
// EaULoss fused single-kernel reduction.
// 4 float4-pairs per thread, all 8 LDG.128 front-batched (small enough that
// ptxas keeps them in registers and issues them back-to-back -> high MLP).
//   a = (e<=eth) ? (1-tanh e) : tanh e
//   b = (u<=uth) ? (1-tanh u) : tanh u
//   den = sum(a*b);  num = sum(a*b where predicates agree)
//   loss = -log( num/(den+1e-10) + 1e-10 )
// ---------------------------------------------------------------------------

#define NBLK   4096
#define NTHR   256
#define VPT    4            // float4-pairs per thread (fast path)
#define EPS_F  1e-10f

__device__ float g_num[NBLK];
__device__ float g_den[NBLK];
__device__ unsigned int g_count = 0;   // wraps back to 0 every call

__device__ __forceinline__ float fast_tanh(float x) {
    float y;
    asm("tanh.approx.f32 %0, %1;" : "=f"(y) : "f"(x));
    return y;
}

__device__ __forceinline__ void accum(float e, float u, float eth, float uth,
                                      float& num, float& den) {
    float te = fast_tanh(e);
    float tu = fast_tanh(u);
    bool  le = (e <= eth);
    bool  ce = (u <= uth);
    float a  = le ? (1.0f - te) : te;
    float b  = ce ? (1.0f - tu) : tu;
    float v  = a * b;
    den += v;
    if (le == ce) num += v;   // low&certain or high&uncertain
}

__device__ __forceinline__ void accum4(float4 e, float4 u, float eth, float uth,
                                       float& num, float& den) {
    accum(e.x, u.x, eth, uth, num, den);
    accum(e.y, u.y, eth, uth, num, den);
    accum(e.z, u.z, eth, uth, num, den);
    accum(e.w, u.w, eth, uth, num, den);
}

__global__ __launch_bounds__(NTHR)
void eau_fused(const float4* __restrict__ err4,
               const float4* __restrict__ unc4,
               const float*  __restrict__ eth_p,
               const float*  __restrict__ uth_p,
               int nvec, int n_total,
               float* __restrict__ out) {
    // Load scalars first so they don't queue behind the bulk loads.
    const float eth = *eth_p;
    const float uth = *uth_p;

    float num = 0.0f, den = 0.0f;

    const int base   = blockIdx.x * NTHR + threadIdx.x;
    const int stride = NBLK * NTHR;

    if (nvec == stride * VPT) {
        // Exact-shape fast path: issue all 8 LDG.128 up front, then compute.
        float4 e0 = __ldcs(&err4[base + 0 * stride]);
        float4 e1 = __ldcs(&err4[base + 1 * stride]);
        float4 e2 = __ldcs(&err4[base + 2 * stride]);
        float4 e3 = __ldcs(&err4[base + 3 * stride]);
        float4 u0 = __ldcs(&unc4[base + 0 * stride]);
        float4 u1 = __ldcs(&unc4[base + 1 * stride]);
        float4 u2 = __ldcs(&unc4[base + 2 * stride]);
        float4 u3 = __ldcs(&unc4[base + 3 * stride]);

        accum4(e0, u0, eth, uth, num, den);
        accum4(e1, u1, eth, uth, num, den);
        accum4(e2, u2, eth, uth, num, den);
        accum4(e3, u3, eth, uth, num, den);
    } else {
        for (int i = base; i < nvec; i += stride) {
            float4 e = __ldcs(&err4[i]);
            float4 u = __ldcs(&unc4[i]);
            accum4(e, u, eth, uth, num, den);
        }
        // scalar tail
        int rem_start = nvec * 4;
        int rem = n_total - rem_start;
        if (blockIdx.x == 0 && (int)threadIdx.x < rem) {
            const float* ef = (const float*)err4;
            const float* uf = (const float*)unc4;
            int j = rem_start + threadIdx.x;
            accum(ef[j], uf[j], eth, uth, num, den);
        }
    }

    // ---- block reduction ----
    #pragma unroll
    for (int off = 16; off > 0; off >>= 1) {
        num += __shfl_xor_sync(0xFFFFFFFFu, num, off);
        den += __shfl_xor_sync(0xFFFFFFFFu, den, off);
    }

    __shared__ float s_num[NTHR / 32];
    __shared__ float s_den[NTHR / 32];
    int lane = threadIdx.x & 31;
    int wid  = threadIdx.x >> 5;
    if (lane == 0) { s_num[wid] = num; s_den[wid] = den; }
    __syncthreads();
    if (wid == 0) {
        num = (lane < NTHR / 32) ? s_num[lane] : 0.0f;
        den = (lane < NTHR / 32) ? s_den[lane] : 0.0f;
        #pragma unroll
        for (int off = 4; off > 0; off >>= 1) {
            num += __shfl_xor_sync(0xFFFFFFFFu, num, off);
            den += __shfl_xor_sync(0xFFFFFFFFu, den, off);
        }
        if (lane == 0) { g_num[blockIdx.x] = num; g_den[blockIdx.x] = den; }
    }

    // ---- last block finishes ----
    __shared__ bool is_last;
    __threadfence();
    if (threadIdx.x == 0) {
        unsigned prev = atomicInc(&g_count, NBLK - 1);  // wraps to 0 on last
        is_last = (prev == NBLK - 1);
    }
    __syncthreads();

    if (is_last) {
        float fn = 0.0f, fd = 0.0f;
        #pragma unroll
        for (int k = 0; k < NBLK / NTHR; k++) {
            int j = threadIdx.x + k * NTHR;
            fn += g_num[j];
            fd += g_den[j];
        }
        #pragma unroll
        for (int off = 16; off > 0; off >>= 1) {
            fn += __shfl_xor_sync(0xFFFFFFFFu, fn, off);
            fd += __shfl_xor_sync(0xFFFFFFFFu, fd, off);
        }
        if (lane == 0) { s_num[wid] = fn; s_den[wid] = fd; }
        __syncthreads();
        if (wid == 0) {
            fn = (lane < NTHR / 32) ? s_num[lane] : 0.0f;
            fd = (lane < NTHR / 32) ? s_den[lane] : 0.0f;
            #pragma unroll
            for (int off = 4; off > 0; off >>= 1) {
                fn += __shfl_xor_sync(0xFFFFFFFFu, fn, off);
                fd += __shfl_xor_sync(0xFFFFFFFFu, fd, off);
            }
            if (lane == 0) {
                float eau = fn / (fd + EPS_F);
                out[0] = -logf(eau + EPS_F);   // BETA = 1.0
            }
        }
    }
}

extern "C" void kernel_launch(void* const* d_in, const int* in_sizes, int n_in,
                              void* d_out, int out_size) {
    const float* err = (const float*)d_in[0];
    const float* unc = (const float*)d_in[1];
    const float* eth = (const float*)d_in[2];
    const float* uth = (const float*)d_in[3];
    float* out = (float*)d_out;

    int n    = in_sizes[0];
    int nvec = n >> 2;

    eau_fused<<<NBLK, NTHR>>>((const float4*)err, (const float4*)unc,
                              eth, uth, nvec, n, out);
}